// round 2
// baseline (speedup 1.0000x reference)
#include <cuda_runtime.h>
#include <cuda_bf16.h>

#define NFD 32
#define NOD 128
#define PST 129           // padded smem stride (odd -> conflict-free column gather)
#define WARPS_PER_BLOCK 8
#define BLOCK_THREADS (WARPS_PER_BLOCK * 32)

__global__ __launch_bounds__(BLOCK_THREADS, 3)
void slater_det_kernel(const int* __restrict__ n,
                       const float* __restrict__ Phi,
                       float* __restrict__ out,
                       int nsamples)
{
    __shared__ float Phi_sh[NFD * PST];
    __shared__ int   idx_sh[WARPS_PER_BLOCK][NFD];

    const int tid  = threadIdx.x;
    const int lane = tid & 31;
    const int wid  = tid >> 5;

    // Stage Phi (32x128 fp32 = 16KB) into padded shared memory once per block.
    for (int t = tid; t < NFD * NOD; t += BLOCK_THREADS) {
        int i = t >> 7;       // row
        int c = t & 127;      // col
        Phi_sh[i * PST + c] = Phi[t];
    }
    __syncthreads();

    const unsigned FULL = 0xffffffffu;
    const int warps_total = (gridDim.x * BLOCK_THREADS) >> 5;
    int gw = (blockIdx.x * BLOCK_THREADS + tid) >> 5;

    for (int s = gw; s < nsamples; s += warps_total) {
        // ---- Build idx: ranks of the 32 occupied orbitals (ascending index) ----
        // Each lane reads 4 consecutive int32 occupancies (coalesced int4).
        const int4 v = ((const int4*)(n + (size_t)s * NOD))[lane];
        unsigned m4 = (unsigned)(v.x != 0)
                    | ((unsigned)(v.y != 0) << 1)
                    | ((unsigned)(v.z != 0) << 2)
                    | ((unsigned)(v.w != 0) << 3);
        unsigned b0 = __ballot_sync(FULL, v.x != 0);
        unsigned b1 = __ballot_sync(FULL, v.y != 0);
        unsigned b2 = __ballot_sync(FULL, v.z != 0);
        unsigned b3 = __ballot_sync(FULL, v.w != 0);
        unsigned lowmask = (1u << lane) - 1u;
        int base = __popc(b0 & lowmask) + __popc(b1 & lowmask)
                 + __popc(b2 & lowmask) + __popc(b3 & lowmask);

        int r0 = base;
        if (m4 & 1u) idx_sh[wid][r0] = lane * 4 + 0;
        int r1 = r0 + (int)(m4 & 1u);
        if (m4 & 2u) idx_sh[wid][r1] = lane * 4 + 1;
        int r2 = r1 + (int)((m4 >> 1) & 1u);
        if (m4 & 4u) idx_sh[wid][r2] = lane * 4 + 2;
        int r3 = r2 + (int)((m4 >> 2) & 1u);
        if (m4 & 8u) idx_sh[wid][r3] = lane * 4 + 3;
        __syncwarp();

        // ---- Gather: lane i holds row i of the 32x32 matrix in registers ----
        float r[NFD];
        #pragma unroll
        for (int j = 0; j < NFD; j++) {
            int c = idx_sh[wid][j];                 // broadcast LDS (same addr all lanes)
            r[j] = Phi_sh[lane * PST + c];          // conflict-free (stride 129)
        }
        __syncwarp();   // protect idx_sh against next iteration's writes

        // ---- LU with partial pivoting (no physical row swaps) ----
        unsigned active = FULL;   // lanes (rows) not yet chosen as pivot
        float det = 1.0f;
        int inv_cnt = 0;          // permutation inversion count (sign)

        #pragma unroll
        for (int k = 0; k < NFD; k++) {
            // argmax |r[k]| over active lanes: pack (abs bits | lane) and REDUX.MAX.
            // Low 5 mantissa bits sacrificed for the lane id — ties broken by
            // highest lane, fine for pivoting (any near-max pivot is stable).
            float av = fabsf(r[k]);
            unsigned key = (active & (1u << lane))
                         ? ((__float_as_uint(av) & 0xffffffe0u) | (unsigned)lane)
                         : 0u;
            unsigned mx = __reduce_max_sync(FULL, key);
            int p = (int)(mx & 31u);

            float piv = __shfl_sync(FULL, r[k], p);
            inv_cnt += __popc(active & ((1u << p) - 1u));
            active &= ~(1u << p);

            det *= piv;
            float invp = (piv != 0.0f) ? __frcp_rn(piv) : 0.0f;
            float f = (active & (1u << lane)) ? (r[k] * invp) : 0.0f;

            #pragma unroll
            for (int j = k + 1; j < NFD; j++) {
                float pv = __shfl_sync(FULL, r[j], p);   // broadcast pivot row
                r[j] = fmaf(-f, pv, r[j]);
            }
        }

        if (lane == 0)
            out[s] = (inv_cnt & 1) ? -det : det;
    }
}

extern "C" void kernel_launch(void* const* d_in, const int* in_sizes, int n_in,
                              void* d_out, int out_size)
{
    const int*   n_ptr = (const int*)d_in[0];      // n:   (B, 128) int32
    const float* Phi   = (const float*)d_in[1];    // Phi: (32, 128) float32
    float*       out   = (float*)d_out;            // det: (B,) float32

    int nsamples = in_sizes[0] / NOD;              // B = 131072

    // 148 SMs x up to 3 resident blocks; grid-stride over samples so Phi is
    // staged only ~1776 times (~28 MB of L2-resident traffic, negligible).
    int grid = 148 * 3;
    slater_det_kernel<<<grid, BLOCK_THREADS>>>(n_ptr, Phi, out, nsamples);
}